// round 1
// baseline (speedup 1.0000x reference)
#include <cuda_runtime.h>

// Problem constants
#define BB 16
#define DD 64
#define HH 128
#define WW 128
// total elements = 16 * 64 * 128 * 128 = 16777216
#define NTOT 16777216
#define NG   (NTOT / 4)          // float4 groups = 4194304
#define W4   (WW / 4)            // 32 float4 per row
#define ROW4 W4                  // h-stride in float4 units
#define PLANE4 (HH * W4)         // d-stride in float4 units = 4096

#define GRID  2368               // 148 SMs * 16
#define BLOCK 256

__device__ double g_partials[GRID];

__device__ __forceinline__ float warp_reduce(float v) {
    v += __shfl_xor_sync(0xFFFFFFFFu, v, 16);
    v += __shfl_xor_sync(0xFFFFFFFFu, v, 8);
    v += __shfl_xor_sync(0xFFFFFFFFu, v, 4);
    v += __shfl_xor_sync(0xFFFFFFFFu, v, 2);
    v += __shfl_xor_sync(0xFFFFFFFFu, v, 1);
    return v;
}

__global__ __launch_bounds__(BLOCK)
void loss_main_kernel(const float4* __restrict__ in4,
                      const float4* __restrict__ out4,
                      const float4* __restrict__ outp4,
                      const float*  __restrict__ t,
                      const float*  __restrict__ tp,
                      const float4* __restrict__ tgt4,
                      const float*  __restrict__ in_scalar)
{
    const float ALPHA  = 0.0257f;
    const float NORM   = 27353.34765625f;
    const float SRC    = 100000.0f / NORM;
    const float THRESH = (1000.0f - 20.0f) / NORM;

    float acc = 0.0f;
    const int stride = gridDim.x * blockDim.x;

    for (int g = blockIdx.x * blockDim.x + threadIdx.x; g < NG; g += stride) {
        const int w4 = g & (W4 - 1);          // 5 bits
        const int h  = (g >> 5) & (HH - 1);   // 7 bits
        const int d  = (g >> 12) & (DD - 1);  // 6 bits
        const int b  = g >> 18;

        const float4 c = in4[g];

        float4 ym, yp, zm, zp;
        const float4 z4 = make_float4(0.f, 0.f, 0.f, 0.f);
        ym = (h > 0)      ? in4[g - ROW4]   : z4;
        yp = (h < HH - 1) ? in4[g + ROW4]   : z4;
        zm = (d > 0)      ? in4[g - PLANE4] : z4;
        zp = (d < DD - 1) ? in4[g + PLANE4] : z4;

        const float xm0 = (w4 > 0)      ? in_scalar[4 * g - 1] : 0.f;
        const float xp3 = (w4 < W4 - 1) ? in_scalar[4 * g + 4] : 0.f;

        const float invdt = 1.0f / (t[b] - tp[b]);

        const float4 o  = out4[g];
        const float4 op = outp4[g];
        const float4 tg = tgt4[g];

        // unpack into arrays for uniform per-lane loop
        float cc[4] = {c.x, c.y, c.z, c.w};
        float xm[4] = {xm0, c.x, c.y, c.z};
        float xp[4] = {c.y, c.z, c.w, xp3};
        float ymv[4] = {ym.x, ym.y, ym.z, ym.w};
        float ypv[4] = {yp.x, yp.y, yp.z, yp.w};
        float zmv[4] = {zm.x, zm.y, zm.z, zm.w};
        float zpv[4] = {zp.x, zp.y, zp.z, zp.w};
        float ov[4]  = {o.x, o.y, o.z, o.w};
        float opv[4] = {op.x, op.y, op.z, op.w};
        float tgv[4] = {tg.x, tg.y, tg.z, tg.w};

        #pragma unroll
        for (int j = 0; j < 4; j++) {
            float lap = xm[j] + xp[j] + ymv[j] + ypv[j] + zmv[j] + zpv[j]
                        - 6.0f * cc[j];
            float src = (cc[j] > THRESH) ? SRC : 0.0f;
            float td  = (ov[j] - opv[j]) * invdt;
            float res = td - ALPHA * lap - src;
            float e   = ov[j] - tgv[j];
            acc = fmaf(res, res, acc);
            acc = fmaf(e, e, acc);
        }
    }

    // block reduction
    __shared__ float warp_sums[BLOCK / 32];
    float wsum = warp_reduce(acc);
    const int lane = threadIdx.x & 31;
    const int wid  = threadIdx.x >> 5;
    if (lane == 0) warp_sums[wid] = wsum;
    __syncthreads();
    if (wid == 0) {
        float v = (lane < BLOCK / 32) ? warp_sums[lane] : 0.0f;
        v = warp_reduce(v);
        if (lane == 0) g_partials[blockIdx.x] = (double)v;
    }
}

__global__ __launch_bounds__(1024)
void loss_final_kernel(float* __restrict__ out)
{
    __shared__ double sh[32];
    double acc = 0.0;
    for (int i = threadIdx.x; i < GRID; i += blockDim.x)
        acc += g_partials[i];

    // warp reduce doubles via shfl
    for (int s = 16; s > 0; s >>= 1)
        acc += __shfl_xor_sync(0xFFFFFFFFu, acc, s);

    const int lane = threadIdx.x & 31;
    const int wid  = threadIdx.x >> 5;
    if (lane == 0) sh[wid] = acc;
    __syncthreads();
    if (wid == 0) {
        double v = (lane < 32) ? sh[lane] : 0.0;
        for (int s = 16; s > 0; s >>= 1)
            v += __shfl_xor_sync(0xFFFFFFFFu, v, s);
        if (lane == 0)
            out[0] = (float)(v / (double)NTOT);
    }
}

extern "C" void kernel_launch(void* const* d_in, const int* in_sizes, int n_in,
                              void* d_out, int out_size)
{
    const float* in_p   = (const float*)d_in[0];
    const float* out_p  = (const float*)d_in[1];
    const float* outp_p = (const float*)d_in[2];
    const float* t_p    = (const float*)d_in[3];
    const float* tp_p   = (const float*)d_in[4];
    const float* tgt_p  = (const float*)d_in[5];

    loss_main_kernel<<<GRID, BLOCK>>>(
        (const float4*)in_p, (const float4*)out_p, (const float4*)outp_p,
        t_p, tp_p, (const float4*)tgt_p, in_p);
    loss_final_kernel<<<1, 1024>>>((float*)d_out);
}

// round 2
// speedup vs baseline: 1.0043x; 1.0043x over previous
#include <cuda_runtime.h>

// Problem: B=16, C=1, D=64, H=128, W=128, fp32
#define BB 16
#define DD 64
#define HH 128
#define WW 128
#define NTOT 16777216               // total elements
#define W4   (WW / 4)               // 32 float4 per row
#define ROW4 W4
#define PLANE4 (HH * W4)            // 4096 float4 per d-plane

#define DCHUNK 16                   // d-planes walked per thread
#define BLOCK 256
#define NCOL  (BB * (DD / DCHUNK) * HH * W4)   // 262144 columns
#define GRID_MAIN (NCOL / BLOCK)               // 1024 blocks

__device__ double       g_partials[GRID_MAIN];
__device__ unsigned int g_count = 0;

__device__ __forceinline__ float warp_reduce(float v) {
    v += __shfl_xor_sync(0xFFFFFFFFu, v, 16);
    v += __shfl_xor_sync(0xFFFFFFFFu, v, 8);
    v += __shfl_xor_sync(0xFFFFFFFFu, v, 4);
    v += __shfl_xor_sync(0xFFFFFFFFu, v, 2);
    v += __shfl_xor_sync(0xFFFFFFFFu, v, 1);
    return v;
}

__global__ __launch_bounds__(BLOCK)
void loss_fused_kernel(const float4* __restrict__ in4,
                       const float4* __restrict__ out4,
                       const float4* __restrict__ outp4,
                       const float*  __restrict__ t,
                       const float*  __restrict__ tp,
                       const float4* __restrict__ tgt4,
                       const float*  __restrict__ in_scalar,
                       float*        __restrict__ out)
{
    const float ALPHA  = 0.0257f;
    const float NORM   = 27353.34765625f;
    const float SRC    = 100000.0f / NORM;
    const float THRESH = (1000.0f - 20.0f) / NORM;
    const float4 z4 = make_float4(0.f, 0.f, 0.f, 0.f);

    const int col = blockIdx.x * BLOCK + threadIdx.x;
    const int w4  = col & (W4 - 1);          // 5 bits
    const int h   = (col >> 5) & (HH - 1);   // 7 bits
    const int dc  = (col >> 12) & (DD / DCHUNK - 1); // 2 bits
    const int b   = col >> 14;

    const int d0 = dc * DCHUNK;
    const int g0 = ((b * DD + d0) * HH + h) * W4 + w4;

    const float invdt = 1.0f / (t[b] - tp[b]);
    const bool has_ym = (h > 0);
    const bool has_yp = (h < HH - 1);
    const bool has_xm = (w4 > 0);
    const bool has_xp = (w4 < W4 - 1);

    // register-rotated z planes
    float4 zm = (d0 > 0) ? in4[g0 - PLANE4] : z4;
    float4 c  = in4[g0];

    float acc = 0.0f;

    #pragma unroll 4
    for (int i = 0; i < DCHUNK; i++) {
        const int d = d0 + i;
        const int g = g0 + i * PLANE4;

        const float4 zp = (d < DD - 1) ? in4[g + PLANE4] : z4;
        const float4 ym = has_ym ? in4[g - ROW4] : z4;
        const float4 yp = has_yp ? in4[g + ROW4] : z4;
        const float xm0 = has_xm ? in_scalar[4 * g - 1] : 0.f;
        const float xp3 = has_xp ? in_scalar[4 * g + 4] : 0.f;

        const float4 o  = out4[g];
        const float4 op = outp4[g];
        const float4 tg = tgt4[g];

        const float cc[4]  = {c.x, c.y, c.z, c.w};
        const float xm[4]  = {xm0, c.x, c.y, c.z};
        const float xp[4]  = {c.y, c.z, c.w, xp3};
        const float ymv[4] = {ym.x, ym.y, ym.z, ym.w};
        const float ypv[4] = {yp.x, yp.y, yp.z, yp.w};
        const float zmv[4] = {zm.x, zm.y, zm.z, zm.w};
        const float zpv[4] = {zp.x, zp.y, zp.z, zp.w};
        const float ov[4]  = {o.x, o.y, o.z, o.w};
        const float opv[4] = {op.x, op.y, op.z, op.w};
        const float tgv[4] = {tg.x, tg.y, tg.z, tg.w};

        #pragma unroll
        for (int j = 0; j < 4; j++) {
            float lap = xm[j] + xp[j] + ymv[j] + ypv[j] + zmv[j] + zpv[j]
                        - 6.0f * cc[j];
            float src = (cc[j] > THRESH) ? SRC : 0.0f;
            float td  = (ov[j] - opv[j]) * invdt;
            float res = td - ALPHA * lap - src;
            float e   = ov[j] - tgv[j];
            acc = fmaf(res, res, acc);
            acc = fmaf(e, e, acc);
        }

        zm = c;
        c  = zp;
    }

    // ── block reduction ──
    __shared__ float warp_sums[BLOCK / 32];
    float wsum = warp_reduce(acc);
    const int lane = threadIdx.x & 31;
    const int wid  = threadIdx.x >> 5;
    if (lane == 0) warp_sums[wid] = wsum;
    __syncthreads();
    if (wid == 0) {
        float v = (lane < BLOCK / 32) ? warp_sums[lane] : 0.0f;
        v = warp_reduce(v);
        if (lane == 0) g_partials[blockIdx.x] = (double)v;
    }

    // ── last-block-done global reduction (threadFenceReduction pattern) ──
    __shared__ bool amLast;
    __threadfence();
    if (threadIdx.x == 0) {
        unsigned int ticket = atomicInc(&g_count, GRID_MAIN - 1); // wraps to 0
        amLast = (ticket == GRID_MAIN - 1);
    }
    __syncthreads();

    if (amLast) {
        __shared__ double sd[BLOCK];
        double v = 0.0;
        // fixed order: i, i+256, i+512, i+768 → deterministic
        for (int i = threadIdx.x; i < GRID_MAIN; i += BLOCK)
            v += g_partials[i];
        sd[threadIdx.x] = v;
        __syncthreads();
        #pragma unroll
        for (int s = BLOCK / 2; s > 0; s >>= 1) {
            if (threadIdx.x < s) sd[threadIdx.x] += sd[threadIdx.x + s];
            __syncthreads();
        }
        if (threadIdx.x == 0)
            out[0] = (float)(sd[0] / (double)NTOT);
    }
}

extern "C" void kernel_launch(void* const* d_in, const int* in_sizes, int n_in,
                              void* d_out, int out_size)
{
    const float* in_p   = (const float*)d_in[0];
    const float* out_p  = (const float*)d_in[1];
    const float* outp_p = (const float*)d_in[2];
    const float* t_p    = (const float*)d_in[3];
    const float* tp_p   = (const float*)d_in[4];
    const float* tgt_p  = (const float*)d_in[5];

    loss_fused_kernel<<<GRID_MAIN, BLOCK>>>(
        (const float4*)in_p, (const float4*)out_p, (const float4*)outp_p,
        t_p, tp_p, (const float4*)tgt_p, in_p, (float*)d_out);
}

// round 3
// speedup vs baseline: 1.1934x; 1.1882x over previous
#include <cuda_runtime.h>

// Problem: B=16, C=1, D=64, H=128, W=128, fp32
#define BB 16
#define DD 64
#define HH 128
#define WW 128
#define NTOT 16777216               // total elements
#define W4   (WW / 4)               // 32 float4 per row  (== warpsize!)
#define ROW4 W4
#define PLANE4 (HH * W4)            // 4096 float4 per d-plane

#define DCHUNK 8                    // d-planes walked per thread
#define BLOCK 256
#define NCOL  (BB * (DD / DCHUNK) * HH * W4)   // 524288 columns
#define GRID_MAIN (NCOL / BLOCK)               // 2048 blocks

__device__ double       g_partials[GRID_MAIN];
__device__ unsigned int g_count = 0;

__device__ __forceinline__ float warp_reduce(float v) {
    v += __shfl_xor_sync(0xFFFFFFFFu, v, 16);
    v += __shfl_xor_sync(0xFFFFFFFFu, v, 8);
    v += __shfl_xor_sync(0xFFFFFFFFu, v, 4);
    v += __shfl_xor_sync(0xFFFFFFFFu, v, 2);
    v += __shfl_xor_sync(0xFFFFFFFFu, v, 1);
    return v;
}

__global__ __launch_bounds__(BLOCK)
void loss_fused_kernel(const float4* __restrict__ in4,
                       const float4* __restrict__ out4,
                       const float4* __restrict__ outp4,
                       const float*  __restrict__ t,
                       const float*  __restrict__ tp,
                       const float4* __restrict__ tgt4,
                       float*        __restrict__ out)
{
    const float ALPHA  = 0.0257f;
    const float NORM   = 27353.34765625f;
    const float SRC    = 100000.0f / NORM;
    const float THRESH = (1000.0f - 20.0f) / NORM;
    const float4 z4 = make_float4(0.f, 0.f, 0.f, 0.f);
    const unsigned FULL = 0xFFFFFFFFu;

    const int col  = blockIdx.x * BLOCK + threadIdx.x;
    const int lane = threadIdx.x & 31;               // == w4
    const int h    = (col >> 5) & (HH - 1);          // 7 bits
    const int dc   = (col >> 12) & (DD / DCHUNK - 1);// 3 bits
    const int b    = col >> 15;

    const int d0 = dc * DCHUNK;
    const int g0 = ((b * DD + d0) * HH + h) * W4 + lane;

    const float invdt = 1.0f / (t[b] - tp[b]);
    const bool has_ym = (h > 0);
    const bool has_yp = (h < HH - 1);
    const bool has_xm = (lane > 0);
    const bool has_xp = (lane < 31);

    // register-rotated z planes
    float4 zm = (d0 > 0) ? in4[g0 - PLANE4] : z4;
    float4 c  = in4[g0];

    float acc = 0.0f;

    #pragma unroll 4
    for (int i = 0; i < DCHUNK; i++) {
        const int d = d0 + i;
        const int g = g0 + i * PLANE4;

        const float4 zp = (d < DD - 1) ? in4[g + PLANE4] : z4;
        const float4 ym = has_ym ? in4[g - ROW4] : z4;
        const float4 yp = has_yp ? in4[g + ROW4] : z4;

        const float4 o  = __ldcs(&out4[g]);
        const float4 op = __ldcs(&outp4[g]);
        const float4 tg = __ldcs(&tgt4[g]);

        // x-neighbors via warp shuffle (lane == w4, warp spans the full row)
        float xm0 = __shfl_up_sync(FULL, c.w, 1);
        float xp3 = __shfl_down_sync(FULL, c.x, 1);
        xm0 = has_xm ? xm0 : 0.0f;
        xp3 = has_xp ? xp3 : 0.0f;

        const float cc[4]  = {c.x, c.y, c.z, c.w};
        const float xm[4]  = {xm0, c.x, c.y, c.z};
        const float xp[4]  = {c.y, c.z, c.w, xp3};
        const float ymv[4] = {ym.x, ym.y, ym.z, ym.w};
        const float ypv[4] = {yp.x, yp.y, yp.z, yp.w};
        const float zmv[4] = {zm.x, zm.y, zm.z, zm.w};
        const float zpv[4] = {zp.x, zp.y, zp.z, zp.w};
        const float ov[4]  = {o.x, o.y, o.z, o.w};
        const float opv[4] = {op.x, op.y, op.z, op.w};
        const float tgv[4] = {tg.x, tg.y, tg.z, tg.w};

        #pragma unroll
        for (int j = 0; j < 4; j++) {
            float lap = xm[j] + xp[j] + ymv[j] + ypv[j] + zmv[j] + zpv[j]
                        - 6.0f * cc[j];
            float src = (cc[j] > THRESH) ? SRC : 0.0f;
            float td  = (ov[j] - opv[j]) * invdt;
            float res = td - ALPHA * lap - src;
            float e   = ov[j] - tgv[j];
            acc = fmaf(res, res, acc);
            acc = fmaf(e, e, acc);
        }

        zm = c;
        c  = zp;
    }

    // ── block reduction ──
    __shared__ float warp_sums[BLOCK / 32];
    float wsum = warp_reduce(acc);
    const int wid = threadIdx.x >> 5;
    if (lane == 0) warp_sums[wid] = wsum;
    __syncthreads();
    if (wid == 0) {
        float v = (lane < BLOCK / 32) ? warp_sums[lane] : 0.0f;
        v = warp_reduce(v);
        if (lane == 0) g_partials[blockIdx.x] = (double)v;
    }

    // ── last-block-done global reduction ──
    __shared__ bool amLast;
    __threadfence();
    if (threadIdx.x == 0) {
        unsigned int ticket = atomicInc(&g_count, GRID_MAIN - 1); // wraps to 0
        amLast = (ticket == GRID_MAIN - 1);
    }
    __syncthreads();

    if (amLast) {
        __shared__ double sd[BLOCK];
        double v = 0.0;
        for (int i = threadIdx.x; i < GRID_MAIN; i += BLOCK)
            v += g_partials[i];
        sd[threadIdx.x] = v;
        __syncthreads();
        #pragma unroll
        for (int s = BLOCK / 2; s > 0; s >>= 1) {
            if (threadIdx.x < s) sd[threadIdx.x] += sd[threadIdx.x + s];
            __syncthreads();
        }
        if (threadIdx.x == 0)
            out[0] = (float)(sd[0] / (double)NTOT);
    }
}

extern "C" void kernel_launch(void* const* d_in, const int* in_sizes, int n_in,
                              void* d_out, int out_size)
{
    const float* in_p   = (const float*)d_in[0];
    const float* out_p  = (const float*)d_in[1];
    const float* outp_p = (const float*)d_in[2];
    const float* t_p    = (const float*)d_in[3];
    const float* tp_p   = (const float*)d_in[4];
    const float* tgt_p  = (const float*)d_in[5];

    loss_fused_kernel<<<GRID_MAIN, BLOCK>>>(
        (const float4*)in_p, (const float4*)out_p, (const float4*)outp_p,
        t_p, tp_p, (const float4*)tgt_p, (float*)d_out);
}